// round 13
// baseline (speedup 1.0000x reference)
#include <cuda_runtime.h>
#include <cuda_bf16.h>
#include <cstdint>

// Problem shape (fixed)
#define NN 40000
#define HH 128
#define EE 640000
#define BN_EPS 1e-5f

// ---------------- MLP (warp MMA) config ----------------
#define MT 64                         // rows per CTA tile (40000 = 625 * 64 exactly)
#define NBLK (NN / MT)                // 625
#define RS 272                        // smem tile row stride in bytes (128 bf16 + 8 pad)
#define ATILE_B (64 * RS)             // 17408 B
#define BTILE_B (128 * RS)            // 34816 B
// dynamic smem offsets
#define SO_B1F 0
#define SO_B2F 512
#define SO_SUM 1024
#define SO_SQ  1536
#define SO_AH  2048
#define SO_AL  (SO_AH + ATILE_B)
#define SO_BH  (SO_AL + ATILE_B)
#define SO_BL  (SO_BH + BTILE_B)
#define SO_END (SO_BL + BTILE_B)      // 106496 B -> 2 CTAs/SM

// Scratch (static device globals — no runtime allocation allowed)
__device__ __align__(16) float g_out[NN * HH];      // agg + (1+eps)*x
__device__ __align__(16) float g_h2[NN * HH];       // pre-BN layer-2 activations
__device__ __align__(16) float g_stats[4 * HH];     // colsum | colsumsq | scale | shift
__device__ __align__(16) uint16_t g_wh[2][HH * HH]; // W1,W2 bf16 hi
__device__ __align__(16) uint16_t g_wl[2][HH * HH]; // W1,W2 bf16 lo
__device__ int g_rowstart[NN + 1];                  // CSR row offsets (by tgt)
__device__ int g_cursor[NN];                        // fill cursors
__device__ int g_esrc[EE];                          // src ids sorted by tgt
__device__ int g_is_i32;

// ---------------- helpers ----------------
__device__ __forceinline__ uint32_t smem_u32(const void* p) {
    uint32_t a;
    asm("{ .reg .u64 t; cvta.to.shared.u64 t, %1; cvt.u32.u64 %0, t; }" : "=r"(a) : "l"(p));
    return a;
}
__device__ __forceinline__ void ldsm4(uint32_t addr, uint32_t r[4]) {
    asm volatile("ldmatrix.sync.aligned.m8n8.x4.shared.b16 {%0,%1,%2,%3}, [%4];"
                 : "=r"(r[0]), "=r"(r[1]), "=r"(r[2]), "=r"(r[3]) : "r"(addr));
}
__device__ __forceinline__ void mma16816(float d[4], const uint32_t a[4], const uint32_t b[2]) {
    asm volatile(
        "mma.sync.aligned.m16n8k16.row.col.f32.bf16.bf16.f32 "
        "{%0,%1,%2,%3}, {%4,%5,%6,%7}, {%8,%9}, {%0,%1,%2,%3};"
        : "+f"(d[0]), "+f"(d[1]), "+f"(d[2]), "+f"(d[3])
        : "r"(a[0]), "r"(a[1]), "r"(a[2]), "r"(a[3]), "r"(b[0]), "r"(b[1]));
}
__device__ __forceinline__ void pack_hilo(float a, float b, uint32_t& hi, uint32_t& lo) {
    __nv_bfloat162 h = __floats2bfloat162_rn(a, b);          // .x=a(low word), .y=b
    float ra = a - __bfloat162float(h.x);
    float rb = b - __bfloat162float(h.y);
    __nv_bfloat162 l = __floats2bfloat162_rn(ra, rb);
    hi = *reinterpret_cast<uint32_t*>(&h);
    lo = *reinterpret_cast<uint32_t*>(&l);
}
// one 64(Mwarp 32)x128x128 GEMM, hi/lo split (hh + hl + lh), acc += A@B^T
__device__ __forceinline__ void gemm_tile(float acc[2][4][4],
                                          uint32_t aH, uint32_t aL,
                                          uint32_t bH, uint32_t bL) {
    #pragma unroll
    for (int kt = 0; kt < 8; kt++) {
        uint32_t ah[2][4], al[2][4], bh[4][2], bl[4][2];
        #pragma unroll
        for (int mi = 0; mi < 2; mi++) {
            ldsm4(aH + mi * 16 * RS + kt * 32, ah[mi]);
            ldsm4(aL + mi * 16 * RS + kt * 32, al[mi]);
        }
        #pragma unroll
        for (int q = 0; q < 2; q++) {
            uint32_t t[4];
            ldsm4(bH + q * 16 * RS + kt * 32, t);
            bh[2*q][0] = t[0]; bh[2*q][1] = t[1]; bh[2*q+1][0] = t[2]; bh[2*q+1][1] = t[3];
            ldsm4(bL + q * 16 * RS + kt * 32, t);
            bl[2*q][0] = t[0]; bl[2*q][1] = t[1]; bl[2*q+1][0] = t[2]; bl[2*q+1][1] = t[3];
        }
        #pragma unroll
        for (int mi = 0; mi < 2; mi++)
            #pragma unroll
            for (int ni = 0; ni < 4; ni++) {
                mma16816(acc[mi][ni], ah[mi], bh[ni]);   // hi*hi
                mma16816(acc[mi][ni], ah[mi], bl[ni]);   // hi*lo
                mma16816(acc[mi][ni], al[mi], bh[ni]);   // lo*hi
            }
    }
}

// ---------------------------------------------------------------------------
// K0: zero CSR counters + BN accumulators; dtype sniff (block 0)
// ---------------------------------------------------------------------------
__global__ void k_detect(const int* __restrict__ e32) {
    int i = blockIdx.x * 256 + threadIdx.x;
    if (i <= NN) g_rowstart[i] = 0;
    if (i < 2 * HH) g_stats[i] = 0.0f;
    if (i == 0) g_is_i32 = 0;
    if (blockIdx.x == 0) {
        int t = threadIdx.x, nz = 0;
        #pragma unroll
        for (int r = 0; r < 4; r++) nz |= e32[2 * (t + 256 * r) + 1];
        if (__syncthreads_or(nz != 0) && t == 0) g_is_i32 = 1;
    }
}

// K0c: pre-convert W1,W2 -> bf16 hi/lo (row-major global)
__global__ void k_convw(const float* __restrict__ W1, const float* __restrict__ W2) {
    int i = blockIdx.x * 256 + threadIdx.x;        // over 2*128*128/2 float2s
    if (i >= HH * HH) return;
    int m = i >= (HH * HH / 2);
    const float* W = m ? W2 : W1;
    int j = i - m * (HH * HH / 2);
    float2 v = ((const float2*)W)[j];
    uint32_t h, l;
    pack_hilo(v.x, v.y, h, l);
    ((uint32_t*)g_wh[m])[j] = h;
    ((uint32_t*)g_wl[m])[j] = l;
}

// ---------------------------------------------------------------------------
// CSR build: histogram -> scan -> fill
// ---------------------------------------------------------------------------
__global__ void k_hist(const int* __restrict__ e32) {
    int e = blockIdx.x * 256 + threadIdx.x;
    if (e >= EE) return;
    int tgt = g_is_i32 ? e32[EE + e] : e32[2 * (EE + e)];
    atomicAdd(&g_rowstart[tgt + 1], 1);
}

__global__ void __launch_bounds__(1024) k_scan() {   // single block, 40001 entries
    __shared__ int sm_[1024];
    const int C = 40;                                // 1024*40 >= 40001
    int t = threadIdx.x;
    int base = t * C;
    int vals[C];
    int s = 0;
    #pragma unroll 4
    for (int k = 0; k < C; k++) {
        int idx = base + k;
        int v = (idx <= NN) ? g_rowstart[idx] : 0;
        s += v;
        vals[k] = s;                                 // local inclusive scan
    }
    sm_[t] = s;
    __syncthreads();
    for (int d = 1; d < 1024; d <<= 1) {             // Hillis-Steele inclusive
        int v = (t >= d) ? sm_[t - d] : 0;
        __syncthreads();
        sm_[t] += v;
        __syncthreads();
    }
    int off = sm_[t] - s;                            // exclusive offset
    #pragma unroll 4
    for (int k = 0; k < C; k++) {
        int idx = base + k;
        if (idx <= NN) {
            int r = off + vals[k];
            g_rowstart[idx] = r;                     // start offset of node idx
            if (idx < NN) g_cursor[idx] = r;
        }
    }
}

__global__ void k_fill(const int* __restrict__ e32) {
    int e = blockIdx.x * 256 + threadIdx.x;
    if (e >= EE) return;
    int src, tgt;
    if (g_is_i32) { src = e32[e];     tgt = e32[EE + e]; }
    else          { src = e32[2 * e]; tgt = e32[2 * (EE + e)]; }
    int pos = atomicAdd(&g_cursor[tgt], 1);
    g_esrc[pos] = src;
}

// ---------------------------------------------------------------------------
// K1: gather-aggregate. One warp per node:
//   g_out[n] = (1+eps)*x[n] + sum_{src in CSR row n} x[src]
// Coalesced edge-index loads + shfl broadcast; unroll-4 row loads for MLP.
// ---------------------------------------------------------------------------
__global__ void __launch_bounds__(256) k_gather(const float* __restrict__ x,
                                                const float* __restrict__ eps) {
    int t = blockIdx.x * 256 + threadIdx.x;
    int n = t >> 5, lane = t & 31;
    if (n >= NN) return;
    float s = 1.0f + eps[0];
    float4 acc = __ldg((const float4*)(x + (long long)n * HH) + lane);
    acc.x *= s; acc.y *= s; acc.z *= s; acc.w *= s;
    int start = g_rowstart[n], end = g_rowstart[n + 1];
    for (int base = start; base < end; base += 32) {
        int m = min(32, end - base);
        int idx = (lane < m) ? g_esrc[base + lane] : 0;
        int k = 0;
        for (; k + 4 <= m; k += 4) {
            int s0 = __shfl_sync(0xffffffffu, idx, k);
            int s1 = __shfl_sync(0xffffffffu, idx, k + 1);
            int s2 = __shfl_sync(0xffffffffu, idx, k + 2);
            int s3 = __shfl_sync(0xffffffffu, idx, k + 3);
            float4 v0 = __ldg((const float4*)(x + (long long)s0 * HH) + lane);
            float4 v1 = __ldg((const float4*)(x + (long long)s1 * HH) + lane);
            float4 v2 = __ldg((const float4*)(x + (long long)s2 * HH) + lane);
            float4 v3 = __ldg((const float4*)(x + (long long)s3 * HH) + lane);
            acc.x += v0.x + v1.x + v2.x + v3.x;
            acc.y += v0.y + v1.y + v2.y + v3.y;
            acc.z += v0.z + v1.z + v2.z + v3.z;
            acc.w += v0.w + v1.w + v2.w + v3.w;
        }
        for (; k < m; k++) {
            int sk = __shfl_sync(0xffffffffu, idx, k);
            float4 v = __ldg((const float4*)(x + (long long)sk * HH) + lane);
            acc.x += v.x; acc.y += v.y; acc.z += v.z; acc.w += v.w;
        }
    }
    ((float4*)(g_out + (long long)n * HH))[lane] = acc;
}

// ---------------------------------------------------------------------------
// K2: fused MLP on mma.sync bf16 hi/lo split (fp32 accumulate)
// ---------------------------------------------------------------------------
__global__ void __launch_bounds__(256, 2) k_mlp(
    const float* __restrict__ b1, const float* __restrict__ b2)
{
    extern __shared__ char smc[];
    uint32_t sb = smem_u32(smc);
    int tid = threadIdx.x, wid = tid >> 5, lane = tid & 31;
    int wm = wid & 1, wn = wid >> 1;
    int row0 = blockIdx.x * MT;

    float* b1s  = (float*)(smc + SO_B1F);
    float* b2s  = (float*)(smc + SO_B2F);
    float* sSum = (float*)(smc + SO_SUM);
    float* sSq  = (float*)(smc + SO_SQ);
    if (tid < HH) {
        b1s[tid] = b1[tid]; b2s[tid] = b2[tid];
        sSum[tid] = 0.0f;   sSq[tid] = 0.0f;
    }

    // A tile: convert 64x128 f32 -> bf16 hi/lo
    for (int i = tid; i < 64 * 32; i += 256) {
        int r = i >> 5, k0 = (i & 31) * 4;
        float4 v = *(const float4*)(g_out + (long long)(row0 + r) * HH + k0);
        uint32_t h0, l0, h1, l1;
        pack_hilo(v.x, v.y, h0, l0);
        pack_hilo(v.z, v.w, h1, l1);
        int off = r * RS + k0 * 2;
        *(uint2*)(smc + SO_AH + off) = make_uint2(h0, h1);
        *(uint2*)(smc + SO_AL + off) = make_uint2(l0, l1);
    }
    // W1 tile: straight bf16 copy
    for (int i = tid; i < 128 * 16; i += 256) {
        int r = i >> 4, k0 = (i & 15) * 8;
        int off = r * RS + k0 * 2;
        *(uint4*)(smc + SO_BH + off) = *(const uint4*)(g_wh[0] + r * HH + k0);
        *(uint4*)(smc + SO_BL + off) = *(const uint4*)(g_wl[0] + r * HH + k0);
    }
    __syncthreads();

    // ldmatrix addressing
    int aRow = ((lane >> 3) & 1) * 8 + (lane & 7);
    int aCol = (lane >> 4) * 16;
    int bRow = ((lane >> 4) & 1) * 8 + (lane & 7);
    int bCol = ((lane >> 3) & 1) * 16;
    uint32_t aH = sb + SO_AH + (wm * 32 + aRow) * RS + aCol;
    uint32_t aL = sb + SO_AL + (wm * 32 + aRow) * RS + aCol;
    uint32_t bH = sb + SO_BH + (wn * 32 + bRow) * RS + bCol;
    uint32_t bL = sb + SO_BL + (wn * 32 + bRow) * RS + bCol;

    float acc[2][4][4];
    #pragma unroll
    for (int mi = 0; mi < 2; mi++)
        #pragma unroll
        for (int ni = 0; ni < 4; ni++)
            #pragma unroll
            for (int j = 0; j < 4; j++) acc[mi][ni][j] = 0.0f;

    // -------- GEMM1 --------
    gemm_tile(acc, aH, aL, bH, bL);
    __syncthreads();

    // epilogue1: h1 = relu(D1 + b1) -> AH/AL
    {
        int r0 = wm * 32 + (lane >> 2);
        int c0 = 2 * (lane & 3);
        #pragma unroll
        for (int mi = 0; mi < 2; mi++)
            #pragma unroll
            for (int ni = 0; ni < 4; ni++) {
                int c = wn * 32 + ni * 8 + c0;
                int r = r0 + mi * 16;
                float v00 = fmaxf(acc[mi][ni][0] + b1s[c],     0.0f);
                float v01 = fmaxf(acc[mi][ni][1] + b1s[c + 1], 0.0f);
                float v10 = fmaxf(acc[mi][ni][2] + b1s[c],     0.0f);
                float v11 = fmaxf(acc[mi][ni][3] + b1s[c + 1], 0.0f);
                uint32_t h, l;
                pack_hilo(v00, v01, h, l);
                *(uint32_t*)(smc + SO_AH + r * RS + c * 2) = h;
                *(uint32_t*)(smc + SO_AL + r * RS + c * 2) = l;
                pack_hilo(v10, v11, h, l);
                *(uint32_t*)(smc + SO_AH + (r + 8) * RS + c * 2) = h;
                *(uint32_t*)(smc + SO_AL + (r + 8) * RS + c * 2) = l;
            }
    }
    __syncthreads();
    // W2 over W1 slots
    for (int i = tid; i < 128 * 16; i += 256) {
        int r = i >> 4, k0 = (i & 15) * 8;
        int off = r * RS + k0 * 2;
        *(uint4*)(smc + SO_BH + off) = *(const uint4*)(g_wh[1] + r * HH + k0);
        *(uint4*)(smc + SO_BL + off) = *(const uint4*)(g_wl[1] + r * HH + k0);
    }
    __syncthreads();

    #pragma unroll
    for (int mi = 0; mi < 2; mi++)
        #pragma unroll
        for (int ni = 0; ni < 4; ni++)
            #pragma unroll
            for (int j = 0; j < 4; j++) acc[mi][ni][j] = 0.0f;

    // -------- GEMM2 --------
    gemm_tile(acc, aH, aL, bH, bL);

    // epilogue2: h2 = D2 + b2 -> g_h2 ; BN column partials
    {
        int r0 = wm * 32 + (lane >> 2);
        int c0 = 2 * (lane & 3);
        #pragma unroll
        for (int ni = 0; ni < 4; ni++) {
            int c = wn * 32 + ni * 8 + c0;
            float bb0 = b2s[c], bb1 = b2s[c + 1];
            float s0 = 0.f, s1 = 0.f, q0 = 0.f, q1 = 0.f;
            #pragma unroll
            for (int mi = 0; mi < 2; mi++) {
                int rg = row0 + r0 + mi * 16;
                float v00 = acc[mi][ni][0] + bb0;
                float v01 = acc[mi][ni][1] + bb1;
                float v10 = acc[mi][ni][2] + bb0;
                float v11 = acc[mi][ni][3] + bb1;
                *(float2*)(g_h2 + (long long)rg * HH + c)       = make_float2(v00, v01);
                *(float2*)(g_h2 + (long long)(rg + 8) * HH + c) = make_float2(v10, v11);
                s0 += v00 + v10; s1 += v01 + v11;
                q0 += v00 * v00 + v10 * v10;
                q1 += v01 * v01 + v11 * v11;
            }
            atomicAdd(&sSum[c], s0);     atomicAdd(&sSum[c + 1], s1);
            atomicAdd(&sSq[c],  q0);     atomicAdd(&sSq[c + 1],  q1);
        }
    }
    __syncthreads();
    if (tid < HH) {
        atomicAdd(&g_stats[tid],      sSum[tid]);
        atomicAdd(&g_stats[HH + tid], sSq[tid]);
    }
}

// K3: finalize BN stats
__global__ void k_stats(const float* __restrict__ gamma, const float* __restrict__ beta) {
    int c = threadIdx.x;
    float inv_n = 1.0f / (float)NN;
    float mean = g_stats[c] * inv_n;
    float var  = g_stats[HH + c] * inv_n - mean * mean;
    float sc   = gamma[c] * rsqrtf(var + BN_EPS);
    g_stats[2 * HH + c] = sc;
    g_stats[3 * HH + c] = beta[c] - mean * sc;
}

// K4: out = relu(h2 * scale + shift)
__global__ void k_apply(float* __restrict__ out) {
    int i = blockIdx.x * 256 + threadIdx.x;
    if (i >= NN * HH / 4) return;
    int c4 = (i & 31) * 4;
    float4 v  = ((const float4*)g_h2)[i];
    float4 sc = *(const float4*)&g_stats[2 * HH + c4];
    float4 sh = *(const float4*)&g_stats[3 * HH + c4];
    v.x = fmaxf(fmaf(v.x, sc.x, sh.x), 0.0f);
    v.y = fmaxf(fmaf(v.y, sc.y, sh.y), 0.0f);
    v.z = fmaxf(fmaf(v.z, sc.z, sh.z), 0.0f);
    v.w = fmaxf(fmaf(v.w, sc.w, sh.w), 0.0f);
    ((float4*)out)[i] = v;
}

// ---------------------------------------------------------------------------
extern "C" void kernel_launch(void* const* d_in, const int* in_sizes, int n_in,
                              void* d_out, int out_size) {
    const float* x     = (const float*)d_in[0];
    const int*   e32   = (const int*)d_in[1];
    const float* eps   = (const float*)d_in[2];
    const float* W1    = (const float*)d_in[3];
    const float* b1    = (const float*)d_in[4];
    const float* W2    = (const float*)d_in[5];
    const float* b2    = (const float*)d_in[6];
    const float* gamma = (const float*)d_in[7];
    const float* beta  = (const float*)d_in[8];
    float* out = (float*)d_out;

    cudaFuncSetAttribute(k_mlp, cudaFuncAttributeMaxDynamicSharedMemorySize, SO_END);

    k_detect <<<(NN + 256) / 256, 256>>>(e32);
    k_convw  <<<(HH * HH + 255) / 256, 256>>>(W1, W2);
    k_hist   <<<(EE + 255) / 256, 256>>>(e32);
    k_scan   <<<1, 1024>>>();
    k_fill   <<<(EE + 255) / 256, 256>>>(e32);
    k_gather <<<(NN * 32 + 255) / 256, 256>>>(x, eps);
    k_mlp    <<<NBLK, 256, SO_END>>>(b1, b2);
    k_stats  <<<1, HH>>>(gamma, beta);
    k_apply  <<<(NN * HH / 4 + 255) / 256, 256>>>(out);
}

// round 16
// speedup vs baseline: 1.3989x; 1.3989x over previous
#include <cuda_runtime.h>
#include <cuda_bf16.h>
#include <cstdint>

// Problem shape (fixed)
#define NN 40000
#define HH 128
#define EE 640000
#define BN_EPS 1e-5f

// ---------------- MLP (warp MMA) config ----------------
#define MT 64                         // rows per CTA tile (40000 = 625 * 64 exactly)
#define NBLK (NN / MT)                // 625
#define RS 272                        // smem tile row stride in bytes (128 bf16 + 8 pad)
#define ATILE_B (64 * RS)             // 17408 B
#define BTILE_B (128 * RS)            // 34816 B
// dynamic smem offsets
#define SO_B1F 0
#define SO_B2F 512
#define SO_SUM 1024
#define SO_SQ  1536
#define SO_AH  2048
#define SO_AL  (SO_AH + ATILE_B)
#define SO_BH  (SO_AL + ATILE_B)
#define SO_BL  (SO_BH + BTILE_B)
#define SO_END (SO_BL + BTILE_B)      // 106496 B -> 2 CTAs/SM

#define SCAN_BLKS 40                  // 40 * 1024 >= NN+1

// Scratch (static device globals — no runtime allocation allowed)
__device__ __align__(16) float g_out[NN * HH];      // agg + (1+eps)*x
__device__ __align__(16) float g_h2[NN * HH];       // pre-BN layer-2 activations
__device__ __align__(16) float g_stats[4 * HH];     // colsum | colsumsq | scale | shift
__device__ __align__(16) uint16_t g_wh[2][HH * HH]; // W1,W2 bf16 hi
__device__ __align__(16) uint16_t g_wl[2][HH * HH]; // W1,W2 bf16 lo
__device__ int g_rowstart[NN + 1];                  // CSR row offsets (by tgt)
__device__ int g_cursor[NN];                        // fill cursors
__device__ int g_esrc[EE];                          // src ids sorted by tgt
__device__ int g_bsum[SCAN_BLKS];                   // scan block sums
__device__ int g_is_i32;

// ---------------- helpers ----------------
__device__ __forceinline__ uint32_t smem_u32(const void* p) {
    uint32_t a;
    asm("{ .reg .u64 t; cvta.to.shared.u64 t, %1; cvt.u32.u64 %0, t; }" : "=r"(a) : "l"(p));
    return a;
}
__device__ __forceinline__ void ldsm4(uint32_t addr, uint32_t r[4]) {
    asm volatile("ldmatrix.sync.aligned.m8n8.x4.shared.b16 {%0,%1,%2,%3}, [%4];"
                 : "=r"(r[0]), "=r"(r[1]), "=r"(r[2]), "=r"(r[3]) : "r"(addr));
}
__device__ __forceinline__ void mma16816(float d[4], const uint32_t a[4], const uint32_t b[2]) {
    asm volatile(
        "mma.sync.aligned.m16n8k16.row.col.f32.bf16.bf16.f32 "
        "{%0,%1,%2,%3}, {%4,%5,%6,%7}, {%8,%9}, {%0,%1,%2,%3};"
        : "+f"(d[0]), "+f"(d[1]), "+f"(d[2]), "+f"(d[3])
        : "r"(a[0]), "r"(a[1]), "r"(a[2]), "r"(a[3]), "r"(b[0]), "r"(b[1]));
}
__device__ __forceinline__ void pack_hilo(float a, float b, uint32_t& hi, uint32_t& lo) {
    __nv_bfloat162 h = __floats2bfloat162_rn(a, b);          // .x=a(low word), .y=b
    float ra = a - __bfloat162float(h.x);
    float rb = b - __bfloat162float(h.y);
    __nv_bfloat162 l = __floats2bfloat162_rn(ra, rb);
    hi = *reinterpret_cast<uint32_t*>(&h);
    lo = *reinterpret_cast<uint32_t*>(&l);
}
// one 64(Mwarp 32)x128x128 GEMM, hi/lo split (hh + hl + lh), acc += A@B^T
__device__ __forceinline__ void gemm_tile(float acc[2][4][4],
                                          uint32_t aH, uint32_t aL,
                                          uint32_t bH, uint32_t bL) {
    #pragma unroll
    for (int kt = 0; kt < 8; kt++) {
        uint32_t ah[2][4], al[2][4], bh[4][2], bl[4][2];
        #pragma unroll
        for (int mi = 0; mi < 2; mi++) {
            ldsm4(aH + mi * 16 * RS + kt * 32, ah[mi]);
            ldsm4(aL + mi * 16 * RS + kt * 32, al[mi]);
        }
        #pragma unroll
        for (int q = 0; q < 2; q++) {
            uint32_t t[4];
            ldsm4(bH + q * 16 * RS + kt * 32, t);
            bh[2*q][0] = t[0]; bh[2*q][1] = t[1]; bh[2*q+1][0] = t[2]; bh[2*q+1][1] = t[3];
            ldsm4(bL + q * 16 * RS + kt * 32, t);
            bl[2*q][0] = t[0]; bl[2*q][1] = t[1]; bl[2*q+1][0] = t[2]; bl[2*q+1][1] = t[3];
        }
        #pragma unroll
        for (int mi = 0; mi < 2; mi++)
            #pragma unroll
            for (int ni = 0; ni < 4; ni++) {
                mma16816(acc[mi][ni], ah[mi], bh[ni]);   // hi*hi
                mma16816(acc[mi][ni], ah[mi], bl[ni]);   // hi*lo
                mma16816(acc[mi][ni], al[mi], bh[ni]);   // lo*hi
            }
    }
}

// ---------------------------------------------------------------------------
// K0: zero CSR counters + BN accumulators; dtype sniff (block 0)
// ---------------------------------------------------------------------------
__global__ void k_detect(const int* __restrict__ e32) {
    int i = blockIdx.x * 256 + threadIdx.x;
    if (i <= NN) g_rowstart[i] = 0;
    if (i < 2 * HH) g_stats[i] = 0.0f;
    if (i == 0) g_is_i32 = 0;
    if (blockIdx.x == 0) {
        int t = threadIdx.x, nz = 0;
        #pragma unroll
        for (int r = 0; r < 4; r++) nz |= e32[2 * (t + 256 * r) + 1];
        if (__syncthreads_or(nz != 0) && t == 0) g_is_i32 = 1;
    }
}

// K0c: pre-convert W1,W2 -> bf16 hi/lo (row-major global)
__global__ void k_convw(const float* __restrict__ W1, const float* __restrict__ W2) {
    int i = blockIdx.x * 256 + threadIdx.x;        // over 2*128*128/2 float2s
    if (i >= HH * HH) return;
    int m = i >= (HH * HH / 2);
    const float* W = m ? W2 : W1;
    int j = i - m * (HH * HH / 2);
    float2 v = ((const float2*)W)[j];
    uint32_t h, l;
    pack_hilo(v.x, v.y, h, l);
    ((uint32_t*)g_wh[m])[j] = h;
    ((uint32_t*)g_wl[m])[j] = l;
}

// ---------------------------------------------------------------------------
// CSR build: histogram -> hierarchical scan (A/B/C) -> fill
// ---------------------------------------------------------------------------
__global__ void k_hist(const int* __restrict__ e32) {
    int e = blockIdx.x * 256 + threadIdx.x;
    if (e >= EE) return;
    int tgt = g_is_i32 ? e32[EE + e] : e32[2 * (EE + e)];
    atomicAdd(&g_rowstart[tgt + 1], 1);
}

// A: per-block in-place inclusive scan of a 1024-entry slice + block total
__global__ void __launch_bounds__(1024) k_scanA() {
    __shared__ int sm_[1024];
    int b = blockIdx.x, t = threadIdx.x;
    int i = b * 1024 + t;
    int v = (i <= NN) ? g_rowstart[i] : 0;
    sm_[t] = v;
    __syncthreads();
    #pragma unroll
    for (int d = 1; d < 1024; d <<= 1) {
        int u = (t >= d) ? sm_[t - d] : 0;
        __syncthreads();
        sm_[t] += u;
        __syncthreads();
    }
    if (i <= NN) g_rowstart[i] = sm_[t];
    if (t == 1023) g_bsum[b] = sm_[t];
}

// B: exclusive scan of the 40 block sums (one tiny block)
__global__ void k_scanB() {
    __shared__ int sm_[64];
    int t = threadIdx.x;
    int v = (t < SCAN_BLKS) ? g_bsum[t] : 0;
    sm_[t] = v;
    __syncthreads();
    #pragma unroll
    for (int d = 1; d < 64; d <<= 1) {
        int u = (t >= d) ? sm_[t - d] : 0;
        __syncthreads();
        sm_[t] += u;
        __syncthreads();
    }
    if (t < SCAN_BLKS) g_bsum[t] = sm_[t] - v;   // exclusive
}

// C: add block offsets; emit rowstart + fill cursors
__global__ void __launch_bounds__(1024) k_scanC() {
    int b = blockIdx.x, t = threadIdx.x;
    int i = b * 1024 + t;
    if (i <= NN) {
        int r = g_rowstart[i] + g_bsum[b];
        g_rowstart[i] = r;
        if (i < NN) g_cursor[i] = r;
    }
}

__global__ void k_fill(const int* __restrict__ e32) {
    int e = blockIdx.x * 256 + threadIdx.x;
    if (e >= EE) return;
    int src, tgt;
    if (g_is_i32) { src = e32[e];     tgt = e32[EE + e]; }
    else          { src = e32[2 * e]; tgt = e32[2 * (EE + e)]; }
    int pos = atomicAdd(&g_cursor[tgt], 1);
    g_esrc[pos] = src;
}

// ---------------------------------------------------------------------------
// K1: gather-aggregate. One warp per node:
//   g_out[n] = (1+eps)*x[n] + sum_{src in CSR row n} x[src]
// ---------------------------------------------------------------------------
__global__ void __launch_bounds__(256) k_gather(const float* __restrict__ x,
                                                const float* __restrict__ eps) {
    int t = blockIdx.x * 256 + threadIdx.x;
    int n = t >> 5, lane = t & 31;
    if (n >= NN) return;
    float s = 1.0f + eps[0];
    float4 acc = __ldg((const float4*)(x + (long long)n * HH) + lane);
    acc.x *= s; acc.y *= s; acc.z *= s; acc.w *= s;
    int start = g_rowstart[n], end = g_rowstart[n + 1];
    for (int base = start; base < end; base += 32) {
        int m = min(32, end - base);
        int idx = (lane < m) ? g_esrc[base + lane] : 0;
        int k = 0;
        for (; k + 4 <= m; k += 4) {
            int s0 = __shfl_sync(0xffffffffu, idx, k);
            int s1 = __shfl_sync(0xffffffffu, idx, k + 1);
            int s2 = __shfl_sync(0xffffffffu, idx, k + 2);
            int s3 = __shfl_sync(0xffffffffu, idx, k + 3);
            float4 v0 = __ldg((const float4*)(x + (long long)s0 * HH) + lane);
            float4 v1 = __ldg((const float4*)(x + (long long)s1 * HH) + lane);
            float4 v2 = __ldg((const float4*)(x + (long long)s2 * HH) + lane);
            float4 v3 = __ldg((const float4*)(x + (long long)s3 * HH) + lane);
            acc.x += v0.x + v1.x + v2.x + v3.x;
            acc.y += v0.y + v1.y + v2.y + v3.y;
            acc.z += v0.z + v1.z + v2.z + v3.z;
            acc.w += v0.w + v1.w + v2.w + v3.w;
        }
        for (; k < m; k++) {
            int sk = __shfl_sync(0xffffffffu, idx, k);
            float4 v = __ldg((const float4*)(x + (long long)sk * HH) + lane);
            acc.x += v.x; acc.y += v.y; acc.z += v.z; acc.w += v.w;
        }
    }
    ((float4*)(g_out + (long long)n * HH))[lane] = acc;
}

// ---------------------------------------------------------------------------
// K2: fused MLP on mma.sync bf16 hi/lo split (fp32 accumulate)
// ---------------------------------------------------------------------------
__global__ void __launch_bounds__(256, 2) k_mlp(
    const float* __restrict__ b1, const float* __restrict__ b2)
{
    extern __shared__ char smc[];
    uint32_t sb = smem_u32(smc);
    int tid = threadIdx.x, wid = tid >> 5, lane = tid & 31;
    int wm = wid & 1, wn = wid >> 1;
    int row0 = blockIdx.x * MT;

    float* b1s  = (float*)(smc + SO_B1F);
    float* b2s  = (float*)(smc + SO_B2F);
    float* sSum = (float*)(smc + SO_SUM);
    float* sSq  = (float*)(smc + SO_SQ);
    if (tid < HH) {
        b1s[tid] = b1[tid]; b2s[tid] = b2[tid];
        sSum[tid] = 0.0f;   sSq[tid] = 0.0f;
    }

    // A tile: convert 64x128 f32 -> bf16 hi/lo
    for (int i = tid; i < 64 * 32; i += 256) {
        int r = i >> 5, k0 = (i & 31) * 4;
        float4 v = *(const float4*)(g_out + (long long)(row0 + r) * HH + k0);
        uint32_t h0, l0, h1, l1;
        pack_hilo(v.x, v.y, h0, l0);
        pack_hilo(v.z, v.w, h1, l1);
        int off = r * RS + k0 * 2;
        *(uint2*)(smc + SO_AH + off) = make_uint2(h0, h1);
        *(uint2*)(smc + SO_AL + off) = make_uint2(l0, l1);
    }
    // W1 tile: straight bf16 copy
    for (int i = tid; i < 128 * 16; i += 256) {
        int r = i >> 4, k0 = (i & 15) * 8;
        int off = r * RS + k0 * 2;
        *(uint4*)(smc + SO_BH + off) = *(const uint4*)(g_wh[0] + r * HH + k0);
        *(uint4*)(smc + SO_BL + off) = *(const uint4*)(g_wl[0] + r * HH + k0);
    }
    __syncthreads();

    // ldmatrix addressing
    int aRow = ((lane >> 3) & 1) * 8 + (lane & 7);
    int aCol = (lane >> 4) * 16;
    int bRow = ((lane >> 4) & 1) * 8 + (lane & 7);
    int bCol = ((lane >> 3) & 1) * 16;
    uint32_t aH = sb + SO_AH + (wm * 32 + aRow) * RS + aCol;
    uint32_t aL = sb + SO_AL + (wm * 32 + aRow) * RS + aCol;
    uint32_t bH = sb + SO_BH + (wn * 32 + bRow) * RS + bCol;
    uint32_t bL = sb + SO_BL + (wn * 32 + bRow) * RS + bCol;

    float acc[2][4][4];
    #pragma unroll
    for (int mi = 0; mi < 2; mi++)
        #pragma unroll
        for (int ni = 0; ni < 4; ni++)
            #pragma unroll
            for (int j = 0; j < 4; j++) acc[mi][ni][j] = 0.0f;

    // -------- GEMM1 --------
    gemm_tile(acc, aH, aL, bH, bL);
    __syncthreads();

    // epilogue1: h1 = relu(D1 + b1) -> AH/AL
    {
        int r0 = wm * 32 + (lane >> 2);
        int c0 = 2 * (lane & 3);
        #pragma unroll
        for (int mi = 0; mi < 2; mi++)
            #pragma unroll
            for (int ni = 0; ni < 4; ni++) {
                int c = wn * 32 + ni * 8 + c0;
                int r = r0 + mi * 16;
                float v00 = fmaxf(acc[mi][ni][0] + b1s[c],     0.0f);
                float v01 = fmaxf(acc[mi][ni][1] + b1s[c + 1], 0.0f);
                float v10 = fmaxf(acc[mi][ni][2] + b1s[c],     0.0f);
                float v11 = fmaxf(acc[mi][ni][3] + b1s[c + 1], 0.0f);
                uint32_t h, l;
                pack_hilo(v00, v01, h, l);
                *(uint32_t*)(smc + SO_AH + r * RS + c * 2) = h;
                *(uint32_t*)(smc + SO_AL + r * RS + c * 2) = l;
                pack_hilo(v10, v11, h, l);
                *(uint32_t*)(smc + SO_AH + (r + 8) * RS + c * 2) = h;
                *(uint32_t*)(smc + SO_AL + (r + 8) * RS + c * 2) = l;
            }
    }
    __syncthreads();
    // W2 over W1 slots
    for (int i = tid; i < 128 * 16; i += 256) {
        int r = i >> 4, k0 = (i & 15) * 8;
        int off = r * RS + k0 * 2;
        *(uint4*)(smc + SO_BH + off) = *(const uint4*)(g_wh[1] + r * HH + k0);
        *(uint4*)(smc + SO_BL + off) = *(const uint4*)(g_wl[1] + r * HH + k0);
    }
    __syncthreads();

    #pragma unroll
    for (int mi = 0; mi < 2; mi++)
        #pragma unroll
        for (int ni = 0; ni < 4; ni++)
            #pragma unroll
            for (int j = 0; j < 4; j++) acc[mi][ni][j] = 0.0f;

    // -------- GEMM2 --------
    gemm_tile(acc, aH, aL, bH, bL);

    // epilogue2: h2 = D2 + b2 -> g_h2 ; BN column partials
    {
        int r0 = wm * 32 + (lane >> 2);
        int c0 = 2 * (lane & 3);
        #pragma unroll
        for (int ni = 0; ni < 4; ni++) {
            int c = wn * 32 + ni * 8 + c0;
            float bb0 = b2s[c], bb1 = b2s[c + 1];
            float s0 = 0.f, s1 = 0.f, q0 = 0.f, q1 = 0.f;
            #pragma unroll
            for (int mi = 0; mi < 2; mi++) {
                int rg = row0 + r0 + mi * 16;
                float v00 = acc[mi][ni][0] + bb0;
                float v01 = acc[mi][ni][1] + bb1;
                float v10 = acc[mi][ni][2] + bb0;
                float v11 = acc[mi][ni][3] + bb1;
                *(float2*)(g_h2 + (long long)rg * HH + c)       = make_float2(v00, v01);
                *(float2*)(g_h2 + (long long)(rg + 8) * HH + c) = make_float2(v10, v11);
                s0 += v00 + v10; s1 += v01 + v11;
                q0 += v00 * v00 + v10 * v10;
                q1 += v01 * v01 + v11 * v11;
            }
            atomicAdd(&sSum[c], s0);     atomicAdd(&sSum[c + 1], s1);
            atomicAdd(&sSq[c],  q0);     atomicAdd(&sSq[c + 1],  q1);
        }
    }
    __syncthreads();
    if (tid < HH) {
        atomicAdd(&g_stats[tid],      sSum[tid]);
        atomicAdd(&g_stats[HH + tid], sSq[tid]);
    }
}

// K3: finalize BN stats
__global__ void k_stats(const float* __restrict__ gamma, const float* __restrict__ beta) {
    int c = threadIdx.x;
    float inv_n = 1.0f / (float)NN;
    float mean = g_stats[c] * inv_n;
    float var  = g_stats[HH + c] * inv_n - mean * mean;
    float sc   = gamma[c] * rsqrtf(var + BN_EPS);
    g_stats[2 * HH + c] = sc;
    g_stats[3 * HH + c] = beta[c] - mean * sc;
}

// K4: out = relu(h2 * scale + shift)
__global__ void k_apply(float* __restrict__ out) {
    int i = blockIdx.x * 256 + threadIdx.x;
    if (i >= NN * HH / 4) return;
    int c4 = (i & 31) * 4;
    float4 v  = ((const float4*)g_h2)[i];
    float4 sc = *(const float4*)&g_stats[2 * HH + c4];
    float4 sh = *(const float4*)&g_stats[3 * HH + c4];
    v.x = fmaxf(fmaf(v.x, sc.x, sh.x), 0.0f);
    v.y = fmaxf(fmaf(v.y, sc.y, sh.y), 0.0f);
    v.z = fmaxf(fmaf(v.z, sc.z, sh.z), 0.0f);
    v.w = fmaxf(fmaf(v.w, sc.w, sh.w), 0.0f);
    ((float4*)out)[i] = v;
}

// ---------------------------------------------------------------------------
extern "C" void kernel_launch(void* const* d_in, const int* in_sizes, int n_in,
                              void* d_out, int out_size) {
    const float* x     = (const float*)d_in[0];
    const int*   e32   = (const int*)d_in[1];
    const float* eps   = (const float*)d_in[2];
    const float* W1    = (const float*)d_in[3];
    const float* b1    = (const float*)d_in[4];
    const float* W2    = (const float*)d_in[5];
    const float* b2    = (const float*)d_in[6];
    const float* gamma = (const float*)d_in[7];
    const float* beta  = (const float*)d_in[8];
    float* out = (float*)d_out;

    cudaFuncSetAttribute(k_mlp, cudaFuncAttributeMaxDynamicSharedMemorySize, SO_END);

    k_detect <<<(NN + 256) / 256, 256>>>(e32);
    k_convw  <<<(HH * HH + 255) / 256, 256>>>(W1, W2);
    k_hist   <<<(EE + 255) / 256, 256>>>(e32);
    k_scanA  <<<SCAN_BLKS, 1024>>>();
    k_scanB  <<<1, 64>>>();
    k_scanC  <<<SCAN_BLKS, 1024>>>();
    k_fill   <<<(EE + 255) / 256, 256>>>(e32);
    k_gather <<<(NN * 32 + 255) / 256, 256>>>(x, eps);
    k_mlp    <<<NBLK, 256, SO_END>>>(b1, b2);
    k_stats  <<<1, HH>>>(gamma, beta);
    k_apply  <<<(NN * HH / 4 + 255) / 256, 256>>>(out);
}

// round 17
// speedup vs baseline: 1.4703x; 1.0511x over previous
#include <cuda_runtime.h>
#include <cuda_bf16.h>
#include <cstdint>

// Problem shape (fixed)
#define NN 40000
#define HH 128
#define EE 640000
#define BN_EPS 1e-5f

// ---------------- MLP (warp MMA) config ----------------
#define MT 64                         // rows per CTA tile (40000 = 625 * 64 exactly)
#define NBLK (NN / MT)                // 625
#define NTHR 512                      // 16 warps
#define RS 272                        // smem tile row stride in bytes (128 bf16 + 8 pad)
#define ATILE_B (64 * RS)             // 17408 B
#define BTILE_B (128 * RS)            // 34816 B
// dynamic smem offsets
#define SO_B1F 0
#define SO_B2F 512
#define SO_SUM 1024
#define SO_SQ  1536
#define SO_AH  2048
#define SO_AL  (SO_AH + ATILE_B)
#define SO_BH  (SO_AL + ATILE_B)
#define SO_BL  (SO_BH + BTILE_B)
#define SO_END (SO_BL + BTILE_B)      // 106496 B -> 2 CTAs/SM (512 thr each)

#define SCAN_BLKS 40                  // 40 * 1024 >= NN+1

// Scratch (static device globals — no runtime allocation allowed)
__device__ __align__(16) uint32_t g_ah[NN * 64];    // aggregated X, bf16-hi pairs
__device__ __align__(16) uint32_t g_al[NN * 64];    // aggregated X, bf16-lo pairs
__device__ __align__(16) float g_h2[NN * HH];       // pre-BN layer-2 activations
__device__ __align__(16) float g_stats[4 * HH];     // colsum | colsumsq | scale | shift
__device__ __align__(16) uint16_t g_wh[2][HH * HH]; // W1,W2 bf16 hi
__device__ __align__(16) uint16_t g_wl[2][HH * HH]; // W1,W2 bf16 lo
__device__ int g_rowstart[NN + 1];                  // CSR row offsets (by tgt)
__device__ int g_cursor[NN];                        // fill cursors
__device__ int g_esrc[EE];                          // src ids sorted by tgt
__device__ int g_bsum[SCAN_BLKS];                   // scan block sums
__device__ int g_is_i32;

// ---------------- helpers ----------------
__device__ __forceinline__ uint32_t smem_u32(const void* p) {
    uint32_t a;
    asm("{ .reg .u64 t; cvta.to.shared.u64 t, %1; cvt.u32.u64 %0, t; }" : "=r"(a) : "l"(p));
    return a;
}
__device__ __forceinline__ void ldsm4(uint32_t addr, uint32_t r[4]) {
    asm volatile("ldmatrix.sync.aligned.m8n8.x4.shared.b16 {%0,%1,%2,%3}, [%4];"
                 : "=r"(r[0]), "=r"(r[1]), "=r"(r[2]), "=r"(r[3]) : "r"(addr));
}
__device__ __forceinline__ void mma16816(float d[4], const uint32_t a[4], const uint32_t b[2]) {
    asm volatile(
        "mma.sync.aligned.m16n8k16.row.col.f32.bf16.bf16.f32 "
        "{%0,%1,%2,%3}, {%4,%5,%6,%7}, {%8,%9}, {%0,%1,%2,%3};"
        : "+f"(d[0]), "+f"(d[1]), "+f"(d[2]), "+f"(d[3])
        : "r"(a[0]), "r"(a[1]), "r"(a[2]), "r"(a[3]), "r"(b[0]), "r"(b[1]));
}
__device__ __forceinline__ void pack_hilo(float a, float b, uint32_t& hi, uint32_t& lo) {
    __nv_bfloat162 h = __floats2bfloat162_rn(a, b);          // .x=a(low word), .y=b
    float ra = a - __bfloat162float(h.x);
    float rb = b - __bfloat162float(h.y);
    __nv_bfloat162 l = __floats2bfloat162_rn(ra, rb);
    hi = *reinterpret_cast<uint32_t*>(&h);
    lo = *reinterpret_cast<uint32_t*>(&l);
}
// one warp-tile (32 rows x 16 cols) x K=128 GEMM step, hi/lo split (hh+hl+lh)
__device__ __forceinline__ void gemm_tile(float acc[2][2][4],
                                          uint32_t aH, uint32_t aL,
                                          uint32_t bH, uint32_t bL) {
    #pragma unroll
    for (int kt = 0; kt < 8; kt++) {
        uint32_t ah[2][4], al[2][4], bh[2][2], bl[2][2];
        #pragma unroll
        for (int mi = 0; mi < 2; mi++) {
            ldsm4(aH + mi * 16 * RS + kt * 32, ah[mi]);
            ldsm4(aL + mi * 16 * RS + kt * 32, al[mi]);
        }
        {
            uint32_t t[4];
            ldsm4(bH + kt * 32, t);
            bh[0][0] = t[0]; bh[0][1] = t[1]; bh[1][0] = t[2]; bh[1][1] = t[3];
            ldsm4(bL + kt * 32, t);
            bl[0][0] = t[0]; bl[0][1] = t[1]; bl[1][0] = t[2]; bl[1][1] = t[3];
        }
        #pragma unroll
        for (int mi = 0; mi < 2; mi++)
            #pragma unroll
            for (int ni = 0; ni < 2; ni++) {
                mma16816(acc[mi][ni], ah[mi], bh[ni]);   // hi*hi
                mma16816(acc[mi][ni], ah[mi], bl[ni]);   // hi*lo
                mma16816(acc[mi][ni], al[mi], bh[ni]);   // lo*hi
            }
    }
}

// ---------------------------------------------------------------------------
// K0: zero CSR counters + BN accumulators; dtype sniff (block 0)
// ---------------------------------------------------------------------------
__global__ void k_detect(const int* __restrict__ e32) {
    int i = blockIdx.x * 256 + threadIdx.x;
    if (i <= NN) g_rowstart[i] = 0;
    if (i < 2 * HH) g_stats[i] = 0.0f;
    if (i == 0) g_is_i32 = 0;
    if (blockIdx.x == 0) {
        int t = threadIdx.x, nz = 0;
        #pragma unroll
        for (int r = 0; r < 4; r++) nz |= e32[2 * (t + 256 * r) + 1];
        if (__syncthreads_or(nz != 0) && t == 0) g_is_i32 = 1;
    }
}

// K0c: pre-convert W1,W2 -> bf16 hi/lo (row-major global)
__global__ void k_convw(const float* __restrict__ W1, const float* __restrict__ W2) {
    int i = blockIdx.x * 256 + threadIdx.x;        // over 2*128*128/2 float2s
    if (i >= HH * HH) return;
    int m = i >= (HH * HH / 2);
    const float* W = m ? W2 : W1;
    int j = i - m * (HH * HH / 2);
    float2 v = ((const float2*)W)[j];
    uint32_t h, l;
    pack_hilo(v.x, v.y, h, l);
    ((uint32_t*)g_wh[m])[j] = h;
    ((uint32_t*)g_wl[m])[j] = l;
}

// ---------------------------------------------------------------------------
// CSR build: histogram -> hierarchical scan (A/B/C) -> fill
// ---------------------------------------------------------------------------
__global__ void k_hist(const int* __restrict__ e32) {
    int e = blockIdx.x * 256 + threadIdx.x;
    if (e >= EE) return;
    int tgt = g_is_i32 ? e32[EE + e] : e32[2 * (EE + e)];
    atomicAdd(&g_rowstart[tgt + 1], 1);
}

// A: per-block in-place inclusive scan of a 1024-entry slice + block total
__global__ void __launch_bounds__(1024) k_scanA() {
    __shared__ int sm_[1024];
    int b = blockIdx.x, t = threadIdx.x;
    int i = b * 1024 + t;
    int v = (i <= NN) ? g_rowstart[i] : 0;
    sm_[t] = v;
    __syncthreads();
    #pragma unroll
    for (int d = 1; d < 1024; d <<= 1) {
        int u = (t >= d) ? sm_[t - d] : 0;
        __syncthreads();
        sm_[t] += u;
        __syncthreads();
    }
    if (i <= NN) g_rowstart[i] = sm_[t];
    if (t == 1023) g_bsum[b] = sm_[t];
}

// B: exclusive scan of the 40 block sums (one tiny block)
__global__ void k_scanB() {
    __shared__ int sm_[64];
    int t = threadIdx.x;
    int v = (t < SCAN_BLKS) ? g_bsum[t] : 0;
    sm_[t] = v;
    __syncthreads();
    #pragma unroll
    for (int d = 1; d < 64; d <<= 1) {
        int u = (t >= d) ? sm_[t - d] : 0;
        __syncthreads();
        sm_[t] += u;
        __syncthreads();
    }
    if (t < SCAN_BLKS) g_bsum[t] = sm_[t] - v;   // exclusive
}

// C: add block offsets; emit rowstart + fill cursors
__global__ void __launch_bounds__(1024) k_scanC() {
    int b = blockIdx.x, t = threadIdx.x;
    int i = b * 1024 + t;
    if (i <= NN) {
        int r = g_rowstart[i] + g_bsum[b];
        g_rowstart[i] = r;
        if (i < NN) g_cursor[i] = r;
    }
}

__global__ void k_fill(const int* __restrict__ e32) {
    int e = blockIdx.x * 256 + threadIdx.x;
    if (e >= EE) return;
    int src, tgt;
    if (g_is_i32) { src = e32[e];     tgt = e32[EE + e]; }
    else          { src = e32[2 * e]; tgt = e32[2 * (EE + e)]; }
    int pos = atomicAdd(&g_cursor[tgt], 1);
    g_esrc[pos] = src;
}

// ---------------------------------------------------------------------------
// K1: gather-aggregate. One warp per node:
//   agg = (1+eps)*x[n] + sum_{src in CSR row n} x[src]
// Output written directly as bf16 hi/lo pairs (MLP A-tile element format).
// ---------------------------------------------------------------------------
__global__ void __launch_bounds__(256) k_gather(const float* __restrict__ x,
                                                const float* __restrict__ eps) {
    int t = blockIdx.x * 256 + threadIdx.x;
    int n = t >> 5, lane = t & 31;
    if (n >= NN) return;
    float s = 1.0f + eps[0];
    float4 acc = __ldg((const float4*)(x + (long long)n * HH) + lane);
    acc.x *= s; acc.y *= s; acc.z *= s; acc.w *= s;
    int start = g_rowstart[n], end = g_rowstart[n + 1];
    for (int base = start; base < end; base += 32) {
        int m = min(32, end - base);
        int idx = (lane < m) ? g_esrc[base + lane] : 0;
        int k = 0;
        for (; k + 8 <= m; k += 8) {
            float4 v[8];
            #pragma unroll
            for (int u = 0; u < 8; u++) {
                int sv = __shfl_sync(0xffffffffu, idx, k + u);
                v[u] = __ldg((const float4*)(x + (long long)sv * HH) + lane);
            }
            #pragma unroll
            for (int u = 0; u < 8; u++) {
                acc.x += v[u].x; acc.y += v[u].y; acc.z += v[u].z; acc.w += v[u].w;
            }
        }
        for (; k < m; k++) {
            int sk = __shfl_sync(0xffffffffu, idx, k);
            float4 v = __ldg((const float4*)(x + (long long)sk * HH) + lane);
            acc.x += v.x; acc.y += v.y; acc.z += v.z; acc.w += v.w;
        }
    }
    uint32_t h0, l0, h1, l1;
    pack_hilo(acc.x, acc.y, h0, l0);
    pack_hilo(acc.z, acc.w, h1, l1);
    ((uint2*)g_ah)[n * 32 + lane] = make_uint2(h0, h1);
    ((uint2*)g_al)[n * 32 + lane] = make_uint2(l0, l1);
}

// ---------------------------------------------------------------------------
// K2: fused MLP on mma.sync bf16 hi/lo split (fp32 accumulate), 16 warps.
//   GEMM1: D1 = X @ W1^T  -> h1 = relu(D1+b1) packed back into A tiles
//   GEMM2: D2 = H1 @ W2^T -> h2 = D2 + b2 -> g_h2, + BN column partials
// warp (wm = wid&1, wn = wid>>1): rows wm*32+..32, cols wn*16+..16
// ---------------------------------------------------------------------------
__global__ void __launch_bounds__(NTHR, 2) k_mlp(
    const float* __restrict__ b1, const float* __restrict__ b2)
{
    extern __shared__ char smc[];
    uint32_t sb = smem_u32(smc);
    int tid = threadIdx.x, wid = tid >> 5, lane = tid & 31;
    int wm = wid & 1, wn = wid >> 1;
    int row0 = blockIdx.x * MT;

    float* b1s  = (float*)(smc + SO_B1F);
    float* b2s  = (float*)(smc + SO_B2F);
    float* sSum = (float*)(smc + SO_SUM);
    float* sSq  = (float*)(smc + SO_SQ);
    if (tid < HH) {
        b1s[tid] = b1[tid]; b2s[tid] = b2[tid];
        sSum[tid] = 0.0f;   sSq[tid] = 0.0f;
    }

    // A tile: straight bf16 copy from g_ah/g_al (16B per thread-iter)
    for (int i = tid; i < 64 * 16; i += NTHR) {
        int r = i >> 4, q = i & 15;
        int off = r * RS + q * 16;
        *(uint4*)(smc + SO_AH + off) = *(const uint4*)(g_ah + (row0 + r) * 64 + q * 4);
        *(uint4*)(smc + SO_AL + off) = *(const uint4*)(g_al + (row0 + r) * 64 + q * 4);
    }
    // W1 tile: straight bf16 copy
    for (int i = tid; i < 128 * 16; i += NTHR) {
        int r = i >> 4, k0 = (i & 15) * 8;
        int off = r * RS + k0 * 2;
        *(uint4*)(smc + SO_BH + off) = *(const uint4*)(g_wh[0] + r * HH + k0);
        *(uint4*)(smc + SO_BL + off) = *(const uint4*)(g_wl[0] + r * HH + k0);
    }
    __syncthreads();

    // ldmatrix addressing
    int aRow = ((lane >> 3) & 1) * 8 + (lane & 7);
    int aCol = (lane >> 4) * 16;
    int bRow = ((lane >> 4) & 1) * 8 + (lane & 7);
    int bCol = ((lane >> 3) & 1) * 16;
    uint32_t aH = sb + SO_AH + (wm * 32 + aRow) * RS + aCol;
    uint32_t aL = sb + SO_AL + (wm * 32 + aRow) * RS + aCol;
    uint32_t bH = sb + SO_BH + (wn * 16 + bRow) * RS + bCol;
    uint32_t bL = sb + SO_BL + (wn * 16 + bRow) * RS + bCol;

    float acc[2][2][4];
    #pragma unroll
    for (int mi = 0; mi < 2; mi++)
        #pragma unroll
        for (int ni = 0; ni < 2; ni++)
            #pragma unroll
            for (int j = 0; j < 4; j++) acc[mi][ni][j] = 0.0f;

    // -------- GEMM1 --------
    gemm_tile(acc, aH, aL, bH, bL);
    __syncthreads();   // all reads done before h1 overwrites A tiles

    // epilogue1: h1 = relu(D1 + b1) -> AH/AL
    {
        int r0 = wm * 32 + (lane >> 2);
        int c0 = 2 * (lane & 3);
        #pragma unroll
        for (int mi = 0; mi < 2; mi++)
            #pragma unroll
            for (int ni = 0; ni < 2; ni++) {
                int c = wn * 16 + ni * 8 + c0;
                int r = r0 + mi * 16;
                float v00 = fmaxf(acc[mi][ni][0] + b1s[c],     0.0f);
                float v01 = fmaxf(acc[mi][ni][1] + b1s[c + 1], 0.0f);
                float v10 = fmaxf(acc[mi][ni][2] + b1s[c],     0.0f);
                float v11 = fmaxf(acc[mi][ni][3] + b1s[c + 1], 0.0f);
                uint32_t h, l;
                pack_hilo(v00, v01, h, l);
                *(uint32_t*)(smc + SO_AH + r * RS + c * 2) = h;
                *(uint32_t*)(smc + SO_AL + r * RS + c * 2) = l;
                pack_hilo(v10, v11, h, l);
                *(uint32_t*)(smc + SO_AH + (r + 8) * RS + c * 2) = h;
                *(uint32_t*)(smc + SO_AL + (r + 8) * RS + c * 2) = l;
            }
    }
    __syncthreads();
    // W2 over W1 slots
    for (int i = tid; i < 128 * 16; i += NTHR) {
        int r = i >> 4, k0 = (i & 15) * 8;
        int off = r * RS + k0 * 2;
        *(uint4*)(smc + SO_BH + off) = *(const uint4*)(g_wh[1] + r * HH + k0);
        *(uint4*)(smc + SO_BL + off) = *(const uint4*)(g_wl[1] + r * HH + k0);
    }
    __syncthreads();

    #pragma unroll
    for (int mi = 0; mi < 2; mi++)
        #pragma unroll
        for (int ni = 0; ni < 2; ni++)
            #pragma unroll
            for (int j = 0; j < 4; j++) acc[mi][ni][j] = 0.0f;

    // -------- GEMM2 --------
    gemm_tile(acc, aH, aL, bH, bL);

    // epilogue2: h2 = D2 + b2 -> g_h2 ; BN column partials
    {
        int r0 = wm * 32 + (lane >> 2);
        int c0 = 2 * (lane & 3);
        #pragma unroll
        for (int ni = 0; ni < 2; ni++) {
            int c = wn * 16 + ni * 8 + c0;
            float bb0 = b2s[c], bb1 = b2s[c + 1];
            float s0 = 0.f, s1 = 0.f, q0 = 0.f, q1 = 0.f;
            #pragma unroll
            for (int mi = 0; mi < 2; mi++) {
                int rg = row0 + r0 + mi * 16;
                float v00 = acc[mi][ni][0] + bb0;
                float v01 = acc[mi][ni][1] + bb1;
                float v10 = acc[mi][ni][2] + bb0;
                float v11 = acc[mi][ni][3] + bb1;
                *(float2*)(g_h2 + (long long)rg * HH + c)       = make_float2(v00, v01);
                *(float2*)(g_h2 + (long long)(rg + 8) * HH + c) = make_float2(v10, v11);
                s0 += v00 + v10; s1 += v01 + v11;
                q0 += v00 * v00 + v10 * v10;
                q1 += v01 * v01 + v11 * v11;
            }
            atomicAdd(&sSum[c], s0);     atomicAdd(&sSum[c + 1], s1);
            atomicAdd(&sSq[c],  q0);     atomicAdd(&sSq[c + 1],  q1);
        }
    }
    __syncthreads();
    if (tid < HH) {
        atomicAdd(&g_stats[tid],      sSum[tid]);
        atomicAdd(&g_stats[HH + tid], sSq[tid]);
    }
}

// K3: finalize BN stats
__global__ void k_stats(const float* __restrict__ gamma, const float* __restrict__ beta) {
    int c = threadIdx.x;
    float inv_n = 1.0f / (float)NN;
    float mean = g_stats[c] * inv_n;
    float var  = g_stats[HH + c] * inv_n - mean * mean;
    float sc   = gamma[c] * rsqrtf(var + BN_EPS);
    g_stats[2 * HH + c] = sc;
    g_stats[3 * HH + c] = beta[c] - mean * sc;
}

// K4: out = relu(h2 * scale + shift)
__global__ void k_apply(float* __restrict__ out) {
    int i = blockIdx.x * 256 + threadIdx.x;
    if (i >= NN * HH / 4) return;
    int c4 = (i & 31) * 4;
    float4 v  = ((const float4*)g_h2)[i];
    float4 sc = *(const float4*)&g_stats[2 * HH + c4];
    float4 sh = *(const float4*)&g_stats[3 * HH + c4];
    v.x = fmaxf(fmaf(v.x, sc.x, sh.x), 0.0f);
    v.y = fmaxf(fmaf(v.y, sc.y, sh.y), 0.0f);
    v.z = fmaxf(fmaf(v.z, sc.z, sh.z), 0.0f);
    v.w = fmaxf(fmaf(v.w, sc.w, sh.w), 0.0f);
    ((float4*)out)[i] = v;
}

// ---------------------------------------------------------------------------
extern "C" void kernel_launch(void* const* d_in, const int* in_sizes, int n_in,
                              void* d_out, int out_size) {
    const float* x     = (const float*)d_in[0];
    const int*   e32   = (const int*)d_in[1];
    const float* eps   = (const float*)d_in[2];
    const float* W1    = (const float*)d_in[3];
    const float* b1    = (const float*)d_in[4];
    const float* W2    = (const float*)d_in[5];
    const float* b2    = (const float*)d_in[6];
    const float* gamma = (const float*)d_in[7];
    const float* beta  = (const float*)d_in[8];
    float* out = (float*)d_out;

    cudaFuncSetAttribute(k_mlp, cudaFuncAttributeMaxDynamicSharedMemorySize, SO_END);

    k_detect <<<(NN + 256) / 256, 256>>>(e32);
    k_convw  <<<(HH * HH + 255) / 256, 256>>>(W1, W2);
    k_hist   <<<(EE + 255) / 256, 256>>>(e32);
    k_scanA  <<<SCAN_BLKS, 1024>>>();
    k_scanB  <<<1, 64>>>();
    k_scanC  <<<SCAN_BLKS, 1024>>>();
    k_fill   <<<(EE + 255) / 256, 256>>>(e32);
    k_gather <<<(NN * 32 + 255) / 256, 256>>>(x, eps);
    k_mlp    <<<NBLK, NTHR, SO_END>>>(b1, b2);
    k_stats  <<<1, HH>>>(gamma, beta);
    k_apply  <<<(NN * HH / 4 + 255) / 256, 256>>>(out);
}